// round 17
// baseline (speedup 1.0000x reference)
#include <cuda_runtime.h>
#include <cuda_fp16.h>
#include <math.h>
#include <stdint.h>

#define C_DIM 256
#define NHEAD 4

// ---------------- device scratch (no allocation allowed) ----------------
__device__ float  g_feat [8192*256];
__device__ float  g_proj [8192*256];
__device__ float  g_sub  [16384*256];
__device__ __half g_feath[8192*256];
__device__ __half g_subh [16384*256];
__device__ __half g_oh   [16384*256];
__device__ __half g_hh   [16384*512];
__device__ __half g_t1h  [16384*512];
__device__ __half g_qkv  [16384*768];
__device__ __half g_semh [16384*256];
__device__ __half g_2dh  [2*4096*384];
__device__ __half g_wpackh[5*256*768];
__device__ __half g_mWh  [5*256*256];
__device__ __half g_w1h  [5*512*512];
__device__ __half g_w2h  [5*512*256];
__device__ __half g_dinoh[384*256];

// ---------------- helpers ----------------
__device__ __forceinline__ uint32_t packh2(float a, float b) {
    __half2 h = __floats2half2_rn(a, b);
    return *(uint32_t*)&h;
}
__device__ __forceinline__ void mma_f16(float (&d)[4], const uint32_t (&a)[4],
                                        const uint32_t (&b)[2]) {
    asm volatile(
        "mma.sync.aligned.m16n8k16.row.col.f32.f16.f16.f32 "
        "{%0,%1,%2,%3}, {%4,%5,%6,%7}, {%8,%9}, {%0,%1,%2,%3};"
        : "+f"(d[0]), "+f"(d[1]), "+f"(d[2]), "+f"(d[3])
        : "r"(a[0]), "r"(a[1]), "r"(a[2]), "r"(a[3]), "r"(b[0]), "r"(b[1]));
}
__device__ __forceinline__ void cp16(uint32_t smem_dst, const void* gsrc) {
    asm volatile("cp.async.cg.shared.global [%0], [%1], 16;"
                 :: "r"(smem_dst), "l"(gsrc));
}
#define CP_COMMIT() asm volatile("cp.async.commit_group;" ::: "memory")
#define CP_WAIT(n)  asm volatile("cp.async.wait_group %0;" :: "n"(n) : "memory")
__device__ __forceinline__ void ldsm_x4(uint32_t (&r)[4], uint32_t a) {
    asm volatile("ldmatrix.sync.aligned.m8n8.x4.shared.b16 {%0,%1,%2,%3}, [%4];"
        : "=r"(r[0]), "=r"(r[1]), "=r"(r[2]), "=r"(r[3]) : "r"(a));
}
__device__ __forceinline__ void ldsm_x4_t(uint32_t (&r)[4], uint32_t a) {
    asm volatile("ldmatrix.sync.aligned.m8n8.x4.trans.shared.b16 {%0,%1,%2,%3}, [%4];"
        : "=r"(r[0]), "=r"(r[1]), "=r"(r[2]), "=r"(r[3]) : "r"(a));
}

// ---------------- FP16 GEMM: ldmatrix + cp.async, 4-stage pipeline ----------
// flags: 1=ReLU, 2=half out, 4=scale cols<256 by 0.125 (exact pow2).
#define GA_STRIDE 80
#define GB_STRIDE 272

template<int MT>
__global__ __launch_bounds__(256, 2)
void gemm_h(const __half* __restrict__ A, const __half* __restrict__ B,
            void* __restrict__ Cv, int M, int N, int K,
            int ldb, int ldc, int flags)
{
    constexpr int MC = MT / 32;
    constexpr int BUF = MT * GA_STRIDE + 32 * GB_STRIDE;
    extern __shared__ uint8_t gs[];
    uint32_t sbase = (uint32_t)__cvta_generic_to_shared(gs);
    int tid = threadIdx.x;
    int lane = tid & 31, wid = tid >> 5;
    int l4 = lane >> 2, la3 = lane & 3;
    int wm = (wid & 1) * (MT / 2), wn = (wid >> 1) * 32;
    int rowBase = blockIdx.y * MT, colBase = blockIdx.x << 7;
    int nC = K >> 5;

    int mtx = lane >> 3, rr = lane & 7;
    int a_row = (mtx & 1) * 8 + rr;
    int a_kc  = (mtx >> 1) * 8;
    int b_kr  = (mtx & 1) * 8 + rr;
    int b_nc  = (mtx >> 1) * 8;

#pragma unroll
    for (int s = 0; s < 3; s++) {
        uint32_t sa = sbase + s * BUF;
        uint32_t sbuf = sa + MT * GA_STRIDE;
        int kb = s << 5;
#pragma unroll
        for (int p = 0; p < MT / 64; p++) {
            int t = p * 256 + tid;
            int r = t >> 2, seg = t & 3;
            cp16(sa + r * GA_STRIDE + seg * 16,
                 A + (size_t)(rowBase + r) * K + kb + seg * 8);
        }
#pragma unroll
        for (int p = 0; p < 2; p++) {
            int t = p * 256 + tid;
            int r = t >> 4, seg = t & 15;
            cp16(sbuf + r * GB_STRIDE + seg * 16,
                 B + (size_t)(kb + r) * ldb + colBase + seg * 8);
        }
        CP_COMMIT();
    }

    float acc[MC][4][4] = {};
    for (int ci = 0; ci < nC; ci++) {
        int rem = nC - 1 - ci;
        if (rem >= 2) { CP_WAIT(2); }
        else if (rem == 1) { CP_WAIT(1); }
        else { CP_WAIT(0); }
        __syncthreads();

        uint32_t SAb = sbase + (ci & 3) * BUF;
        uint32_t SBb = SAb + MT * GA_STRIDE;
#pragma unroll
        for (int kt = 0; kt < 2; kt++) {
            int kk = kt * 16;
            uint32_t af[MC][4];
#pragma unroll
            for (int mt = 0; mt < MC; mt++)
                ldsm_x4(af[mt], SAb + (wm + mt * 16 + a_row) * GA_STRIDE + (kk + a_kc) * 2);
            uint32_t bf[2][4];
#pragma unroll
            for (int np = 0; np < 2; np++)
                ldsm_x4_t(bf[np], SBb + (kk + b_kr) * GB_STRIDE + (wn + np * 16 + b_nc) * 2);
#pragma unroll
            for (int mt = 0; mt < MC; mt++)
#pragma unroll
                for (int nt = 0; nt < 4; nt++) {
                    uint32_t bb[2] = {bf[nt >> 1][(nt & 1) * 2],
                                      bf[nt >> 1][(nt & 1) * 2 + 1]};
                    mma_f16(acc[mt][nt], af[mt], bb);
                }
        }
        if (ci + 3 < nC) {
            uint32_t sa = sbase + ((ci + 3) & 3) * BUF;
            uint32_t sbuf = sa + MT * GA_STRIDE;
            int kb = (ci + 3) << 5;
#pragma unroll
            for (int p = 0; p < MT / 64; p++) {
                int t = p * 256 + tid;
                int r = t >> 2, seg = t & 3;
                cp16(sa + r * GA_STRIDE + seg * 16,
                     A + (size_t)(rowBase + r) * K + kb + seg * 8);
            }
#pragma unroll
            for (int p = 0; p < 2; p++) {
                int t = p * 256 + tid;
                int r = t >> 4, seg = t & 15;
                cp16(sbuf + r * GB_STRIDE + seg * 16,
                     B + (size_t)(kb + r) * ldb + colBase + seg * 8);
            }
            CP_COMMIT();
        }
    }

    float scl = ((flags & 4) && colBase < 256) ? 0.125f : 1.0f;
#pragma unroll
    for (int mt = 0; mt < MC; mt++) {
        int r0 = rowBase + wm + mt * 16 + l4;
#pragma unroll
        for (int nt = 0; nt < 4; nt++) {
            int c = colBase + wn + nt * 8 + la3 * 2;
            float v[4] = {acc[mt][nt][0], acc[mt][nt][1], acc[mt][nt][2], acc[mt][nt][3]};
#pragma unroll
            for (int e = 0; e < 4; e++) v[e] *= scl;
            if (flags & 1) {
#pragma unroll
                for (int e = 0; e < 4; e++) v[e] = fmaxf(v[e], 0.f);
            }
            if (flags & 2) {
                __half* Ch = (__half*)Cv;
                *(uint32_t*)&Ch[(size_t)r0 * ldc + c]       = packh2(v[0], v[1]);
                *(uint32_t*)&Ch[(size_t)(r0 + 8) * ldc + c] = packh2(v[2], v[3]);
            } else {
                float* Cf = (float*)Cv;
                *(float2*)(Cf + (size_t)r0 * ldc + c)       = make_float2(v[0], v[1]);
                *(float2*)(Cf + (size_t)(r0 + 8) * ldc + c) = make_float2(v[2], v[3]);
            }
        }
    }
}

// ---------------- fused GEMM(N=256) + LayerNorm epilogue --------------------
#define GLN_ASZ   (32*80)
#define GLN_BSTR  528
#define GLN_STAGE (GLN_ASZ + 32*GLN_BSTR)
#define GLN_SMEM  (4*GLN_STAGE + 1024)

template<int MODE>
__global__ __launch_bounds__(256, 2)
void gemm_ln(const __half* __restrict__ A, const __half* __restrict__ B,
             const float* __restrict__ x, float* __restrict__ outp,
             __half* __restrict__ outh, int M, int K, int ldb)
{
    extern __shared__ uint8_t gs[];
    uint32_t sbase = (uint32_t)__cvta_generic_to_shared(gs);
    float* ps = (float*)(gs + 4 * GLN_STAGE);
    float* pq = ps + 128;
    int tid = threadIdx.x, lane = tid & 31, wid = tid >> 5;
    int l4 = lane >> 2, la3 = lane & 3;
    int wm = (wid & 1) * 16, wn = (wid >> 1) * 64;
    int rowBase = blockIdx.x * 32;
    int nC = K >> 5;
    int mtx = lane >> 3, rr = lane & 7;
    int a_row = (mtx & 1) * 8 + rr, a_kc = (mtx >> 1) * 8;
    int b_kr  = (mtx & 1) * 8 + rr, b_nc = (mtx >> 1) * 8;

#pragma unroll
    for (int s = 0; s < 3; s++) {
        uint32_t sa = sbase + s * GLN_STAGE, sb2 = sa + GLN_ASZ;
        int kb = s << 5;
        if (tid < 128) {
            int r = tid >> 2, seg = tid & 3;
            cp16(sa + r * 80 + seg * 16, A + (size_t)(rowBase + r) * K + kb + seg * 8);
        }
#pragma unroll
        for (int p = 0; p < 4; p++) {
            int t = p * 256 + tid;
            int r = t >> 5, seg = t & 31;
            cp16(sb2 + r * GLN_BSTR + seg * 16, B + (size_t)(kb + r) * ldb + seg * 8);
        }
        CP_COMMIT();
    }

    float acc[8][4] = {};
    for (int ci = 0; ci < nC; ci++) {
        int rem = nC - 1 - ci;
        if (rem >= 2) { CP_WAIT(2); }
        else if (rem == 1) { CP_WAIT(1); }
        else { CP_WAIT(0); }
        __syncthreads();

        uint32_t SAb = sbase + (ci & 3) * GLN_STAGE;
        uint32_t SBb = SAb + GLN_ASZ;
#pragma unroll
        for (int kt = 0; kt < 2; kt++) {
            int kk = kt * 16;
            uint32_t af[4];
            ldsm_x4(af, SAb + (wm + a_row) * 80 + (kk + a_kc) * 2);
            uint32_t bf[4][4];
#pragma unroll
            for (int np = 0; np < 4; np++)
                ldsm_x4_t(bf[np], SBb + (kk + b_kr) * GLN_BSTR + (wn + np * 16 + b_nc) * 2);
#pragma unroll
            for (int nf = 0; nf < 8; nf++) {
                uint32_t bb[2] = {bf[nf >> 1][(nf & 1) * 2], bf[nf >> 1][(nf & 1) * 2 + 1]};
                mma_f16(acc[nf], af, bb);
            }
        }
        if (ci + 3 < nC) {
            uint32_t sa = sbase + ((ci + 3) & 3) * GLN_STAGE, sb2 = sa + GLN_ASZ;
            int kb = (ci + 3) << 5;
            if (tid < 128) {
                int r = tid >> 2, seg = tid & 3;
                cp16(sa + r * 80 + seg * 16, A + (size_t)(rowBase + r) * K + kb + seg * 8);
            }
#pragma unroll
            for (int p = 0; p < 4; p++) {
                int t = p * 256 + tid;
                int r = t >> 5, seg = t & 31;
                cp16(sb2 + r * GLN_BSTR + seg * 16, B + (size_t)(kb + r) * ldb + seg * 8);
            }
            CP_COMMIT();
        }
    }

    float s0 = 0.f, s1 = 0.f, q0 = 0.f, q1 = 0.f;
#pragma unroll
    for (int nf = 0; nf < 8; nf++) {
        s0 += acc[nf][0] + acc[nf][1];
        q0 += acc[nf][0] * acc[nf][0] + acc[nf][1] * acc[nf][1];
        s1 += acc[nf][2] + acc[nf][3];
        q1 += acc[nf][2] * acc[nf][2] + acc[nf][3] * acc[nf][3];
    }
    s0 += __shfl_xor_sync(0xffffffffu, s0, 1); s0 += __shfl_xor_sync(0xffffffffu, s0, 2);
    q0 += __shfl_xor_sync(0xffffffffu, q0, 1); q0 += __shfl_xor_sync(0xffffffffu, q0, 2);
    s1 += __shfl_xor_sync(0xffffffffu, s1, 1); s1 += __shfl_xor_sync(0xffffffffu, s1, 2);
    q1 += __shfl_xor_sync(0xffffffffu, q1, 1); q1 += __shfl_xor_sync(0xffffffffu, q1, 2);
    if (la3 == 0) {
        int r = wm + l4, wnid = wid >> 1;
        ps[r * 4 + wnid] = s0; pq[r * 4 + wnid] = q0;
        ps[(r + 8) * 4 + wnid] = s1; pq[(r + 8) * 4 + wnid] = q1;
    }
    __syncthreads();

    int r0 = wm + l4, r1 = r0 + 8;
    float m0 = (ps[r0*4] + ps[r0*4+1] + ps[r0*4+2] + ps[r0*4+3]) * (1.f / 256.f);
    float v0 = (pq[r0*4] + pq[r0*4+1] + pq[r0*4+2] + pq[r0*4+3]) * (1.f / 256.f) - m0 * m0;
    float is0 = rsqrtf(v0 + 1e-5f);
    float m1 = (ps[r1*4] + ps[r1*4+1] + ps[r1*4+2] + ps[r1*4+3]) * (1.f / 256.f);
    float v1 = (pq[r1*4] + pq[r1*4+1] + pq[r1*4+2] + pq[r1*4+3]) * (1.f / 256.f) - m1 * m1;
    float is1 = rsqrtf(v1 + 1e-5f);

#pragma unroll
    for (int nf = 0; nf < 8; nf++) {
        int c = wn + nf * 8 + la3 * 2;
        float y0 = (acc[nf][0] - m0) * is0, y1 = (acc[nf][1] - m0) * is0;
        float y2 = (acc[nf][2] - m1) * is1, y3 = (acc[nf][3] - m1) * is1;
        if (MODE == 0) {
            *(uint32_t*)&outh[(size_t)(rowBase + r0) * 512 + 256 + c] = packh2(y0, y1);
            *(uint32_t*)&outh[(size_t)(rowBase + r1) * 512 + 256 + c] = packh2(y2, y3);
        } else {
            float xa0 = x[(size_t)(rowBase + r0) * 256 + c];
            float xa1 = x[(size_t)(rowBase + r0) * 256 + c + 1];
            float xb0 = x[(size_t)(rowBase + r1) * 256 + c];
            float xb1 = x[(size_t)(rowBase + r1) * 256 + c + 1];
            float o0 = xa0 + y0, o1 = xa1 + y1, o2 = xb0 + y2, o3 = xb1 + y3;
            *(float2*)(outp + (size_t)(rowBase + r0) * 256 + c) = make_float2(o0, o1);
            *(float2*)(outp + (size_t)(rowBase + r1) * 256 + c) = make_float2(o2, o3);
            *(uint32_t*)&outh[(size_t)(rowBase + r0) * 256 + c] = packh2(o0, o1);
            *(uint32_t*)&outh[(size_t)(rowBase + r1) * 256 + c] = packh2(o2, o3);
        }
    }
    if (MODE == 0) {
#pragma unroll
        for (int p = 0; p < 32; p++) {
            int i = p * 256 + tid;
            int r = i >> 8, c = i & 255;
            outh[(size_t)(rowBase + r) * 512 + c] =
                __float2half(x[(size_t)(rowBase + r) * 256 + c]);
        }
    }
}

// ---------------- FP16 flash attention, templated warp count ----------------
// NW warps, NW*16 q-rows per CTA, kv-tile 64. Q pre-scaled by 0.125.
#define AQS 36
template<int NW>
__global__ __launch_bounds__(NW * 32, 2)
void attn_kernel(const __half* __restrict__ Qp, const __half* __restrict__ KVp,
                 __half* __restrict__ O, int Lq, int Lkv, int kvx)
{
    constexpr int QROWS = NW * 16;
    constexpr int SM_Q = 0;
    constexpr int SM_K = QROWS * AQS;
    constexpr int SM_V = SM_K + 2 * 64 * AQS;
    constexpr int NTHR = NW * 32;
    extern __shared__ uint32_t sm[];
    uint32_t sb = (uint32_t)__cvta_generic_to_shared(sm);
    int tid = threadIdx.x;
    int lane = tid & 31, wid = tid >> 5;
    int l4 = lane >> 2, la3 = lane & 3;
    int qt = blockIdx.x, h = blockIdx.y, b = blockIdx.z;
    int bk = b ^ kvx;
    int wq = wid * 16;
    int mtx = lane >> 3, rr = lane & 7;

    const __half* Qb = Qp + ((size_t)b * Lq + qt * QROWS) * 768 + h * 64;
    const __half* Kb = KVp + (size_t)bk * Lkv * 768 + 256 + h * 64;
    const __half* Vb = Kb + 256;

#pragma unroll
    for (int p = 0; p < 4; p++) {
        int idx = p * NTHR + tid;
        int r = idx >> 3, cg = idx & 7;
        cp16(sb + (SM_Q + r * AQS) * 4 + cg * 16, Qb + (size_t)r * 768 + cg * 8);
    }
#pragma unroll
    for (int p = 0; p < 16 / NW; p++) {
        int idx = p * NTHR + tid;
        int r = idx >> 3, cg = idx & 7;
        cp16(sb + (SM_K + r * AQS) * 4 + cg * 16, Kb + (size_t)r * 768 + cg * 8);
        cp16(sb + (SM_V + r * AQS) * 4 + cg * 16, Vb + (size_t)r * 768 + cg * 8);
    }
    CP_COMMIT();

    uint32_t qa[4][4];
    float oacc[8][4] = {};
    float mrow[2] = {-INFINITY, -INFINITY};
    float lrow[2] = {0.f, 0.f};
    int buf = 0;
    int nTiles = Lkv >> 6;

    for (int t = 0; t < nTiles; t++) {
        if (t + 1 < nTiles) {
            const __half* Kn = Kb + (size_t)(t + 1) * 64 * 768;
            const __half* Vn = Vb + (size_t)(t + 1) * 64 * 768;
            uint32_t kd = sb + (SM_K + (buf ^ 1) * 64 * AQS) * 4;
            uint32_t vd = sb + (SM_V + (buf ^ 1) * 64 * AQS) * 4;
#pragma unroll
            for (int p = 0; p < 16 / NW; p++) {
                int idx = p * NTHR + tid;
                int r = idx >> 3, cg = idx & 7;
                cp16(kd + r * AQS * 4 + cg * 16, Kn + (size_t)r * 768 + cg * 8);
                cp16(vd + r * AQS * 4 + cg * 16, Vn + (size_t)r * 768 + cg * 8);
            }
            CP_COMMIT();
            CP_WAIT(1);
        } else {
            CP_WAIT(0);
        }
        __syncthreads();

        if (t == 0) {
#pragma unroll
            for (int kt = 0; kt < 4; kt++) {
                int kk = kt * 8;
                int r = wq + l4;
                qa[kt][0] = sm[SM_Q + r * AQS + kk + la3];
                qa[kt][1] = sm[SM_Q + (r + 8) * AQS + kk + la3];
                qa[kt][2] = sm[SM_Q + r * AQS + kk + 4 + la3];
                qa[kt][3] = sm[SM_Q + (r + 8) * AQS + kk + 4 + la3];
            }
        }

        uint32_t sbK = sb + (SM_K + buf * 64 * AQS) * 4;
        uint32_t sbV = sb + (SM_V + buf * 64 * AQS) * 4;

        float sacc[8][4] = {};
#pragma unroll
        for (int kt = 0; kt < 4; kt++) {
            int kk = kt * 8;
#pragma unroll
            for (int ng = 0; ng < 4; ng++) {
                uint32_t kf[4];
                ldsm_x4(kf, sbK + ((ng * 16 + (mtx >> 1) * 8 + rr) * AQS
                                   + kk + (mtx & 1) * 4) * 4);
                uint32_t b0[2] = {kf[0], kf[1]};
                uint32_t b1[2] = {kf[2], kf[3]};
                mma_f16(sacc[2 * ng],     qa[kt], b0);
                mma_f16(sacc[2 * ng + 1], qa[kt], b1);
            }
        }

        float mx0 = -INFINITY, mx1 = -INFINITY;
#pragma unroll
        for (int nt = 0; nt < 8; nt++) {
            mx0 = fmaxf(mx0, fmaxf(sacc[nt][0], sacc[nt][1]));
            mx1 = fmaxf(mx1, fmaxf(sacc[nt][2], sacc[nt][3]));
        }
        mx0 = fmaxf(mx0, __shfl_xor_sync(0xffffffffu, mx0, 1));
        mx0 = fmaxf(mx0, __shfl_xor_sync(0xffffffffu, mx0, 2));
        mx1 = fmaxf(mx1, __shfl_xor_sync(0xffffffffu, mx1, 1));
        mx1 = fmaxf(mx1, __shfl_xor_sync(0xffffffffu, mx1, 2));
        float mn0 = fmaxf(mrow[0], mx0), mn1 = fmaxf(mrow[1], mx1);
        float sc0 = __expf(mrow[0] - mn0), sc1 = __expf(mrow[1] - mn1);
        float sum0 = 0.f, sum1 = 0.f;
#pragma unroll
        for (int nt = 0; nt < 8; nt++) {
            sacc[nt][0] = __expf(sacc[nt][0] - mn0);
            sacc[nt][1] = __expf(sacc[nt][1] - mn0);
            sacc[nt][2] = __expf(sacc[nt][2] - mn1);
            sacc[nt][3] = __expf(sacc[nt][3] - mn1);
            sum0 += sacc[nt][0] + sacc[nt][1];
            sum1 += sacc[nt][2] + sacc[nt][3];
        }
        sum0 += __shfl_xor_sync(0xffffffffu, sum0, 1);
        sum0 += __shfl_xor_sync(0xffffffffu, sum0, 2);
        sum1 += __shfl_xor_sync(0xffffffffu, sum1, 1);
        sum1 += __shfl_xor_sync(0xffffffffu, sum1, 2);
        lrow[0] = lrow[0] * sc0 + sum0;
        lrow[1] = lrow[1] * sc1 + sum1;
        mrow[0] = mn0; mrow[1] = mn1;
#pragma unroll
        for (int nt = 0; nt < 8; nt++) {
            oacc[nt][0] *= sc0; oacc[nt][1] *= sc0;
            oacc[nt][2] *= sc1; oacc[nt][3] *= sc1;
        }

        uint32_t pa[4][4];
#pragma unroll
        for (int kt = 0; kt < 4; kt++) {
            pa[kt][0] = packh2(sacc[2*kt][0],   sacc[2*kt][1]);
            pa[kt][1] = packh2(sacc[2*kt][2],   sacc[2*kt][3]);
            pa[kt][2] = packh2(sacc[2*kt+1][0], sacc[2*kt+1][1]);
            pa[kt][3] = packh2(sacc[2*kt+1][2], sacc[2*kt+1][3]);
        }

#pragma unroll
        for (int kt = 0; kt < 4; kt++) {
            int kk16 = kt * 16;
#pragma unroll
            for (int ng = 0; ng < 4; ng++) {
                uint32_t vf[4];
                ldsm_x4_t(vf, sbV + (kk16 + (mtx & 1) * 8 + rr) * AQS * 4
                              + (ng * 16 + (mtx >> 1) * 8) * 2);
                uint32_t b0[2] = {vf[0], vf[1]};
                uint32_t b1[2] = {vf[2], vf[3]};
                mma_f16(oacc[2 * ng],     pa[kt], b0);
                mma_f16(oacc[2 * ng + 1], pa[kt], b1);
            }
        }
        __syncthreads();
        buf ^= 1;
    }

    float inv0 = 1.f / lrow[0], inv1 = 1.f / lrow[1];
    int rg = qt * QROWS + wq + l4;
#pragma unroll
    for (int nt = 0; nt < 8; nt++) {
        int c = h * 64 + nt * 8 + la3 * 2;
        *(uint32_t*)&O[((size_t)b * Lq + rg) * C_DIM + c] =
            packh2(oacc[nt][0] * inv0, oacc[nt][1] * inv0);
        *(uint32_t*)&O[((size_t)b * Lq + rg + 8) * C_DIM + c] =
            packh2(oacc[nt][2] * inv1, oacc[nt][3] * inv1);
    }
}
#define ATTN_SMEM8 ((128 + 256) * AQS * 4)   // 55296
#define ATTN_SMEM4 ((64 + 256) * AQS * 4)    // 46080

// ---------------- misc kernels ----------------
__global__ void add_kernel(float* __restrict__ x, __half* __restrict__ xh,
                           const float* __restrict__ a, int n)
{
    int i = blockIdx.x * 256 + threadIdx.x;
    if (i < n) {
        float v = x[i] + a[i];
        x[i] = v;
        xh[i] = __float2half(v);
    }
}

__global__ void gather_kernel(const float* __restrict__ feat, const int* __restrict__ idx,
                              float* __restrict__ outp, __half* __restrict__ outh,
                              int N, int Lp, int maskNum)
{
    int row = blockIdx.x;
    int g = row / Lp;
    int b = g / maskNum;
    int i = idx[row];
    int c = threadIdx.x;
    float val = 0.f;
    if (i >= 0 && i < N) val = feat[((size_t)b * N + i) * C_DIM + c];
    outp[(size_t)row * C_DIM + c] = val;
    outh[(size_t)row * C_DIM + c] = __float2half(val);
}

__global__ void cvt_h_kernel(const float* __restrict__ s, __half* __restrict__ d, int n)
{
    int i = blockIdx.x * 256 + threadIdx.x;
    if (i < n) d[i] = __float2half(s[i]);
}

__global__ void cvt_weights(const float* qW, const float* kW, const float* vW,
                            const float* mW, const float* w1, const float* w2,
                            const float* dino,
                            __half* wpackh, __half* mWh, __half* w1h, __half* w2h,
                            __half* dinoh)
{
    const int S1 = 5*256*768, S2 = 5*256*256, S3 = 5*512*512, S4 = 5*512*256, S5 = 384*256;
    int i = blockIdx.x * 256 + threadIdx.x;
    if (i < S1) {
        int li = i / (256 * 768), rem = i % (256 * 768);
        int k = rem / 768, j = rem % 768;
        int w = j >> 8, n = j & 255;
        const float* src = (w == 0) ? qW : (w == 1) ? kW : vW;
        wpackh[i] = __float2half(src[(size_t)li * 65536 + k * 256 + n]);
    } else if (i < S1 + S2) {
        mWh[i - S1] = __float2half(mW[i - S1]);
    } else if (i < S1 + S2 + S3) {
        w1h[i - S1 - S2] = __float2half(w1[i - S1 - S2]);
    } else if (i < S1 + S2 + S3 + S4) {
        w2h[i - S1 - S2 - S3] = __float2half(w2[i - S1 - S2 - S3]);
    } else if (i < S1 + S2 + S3 + S4 + S5) {
        dinoh[i - S1 - S2 - S3 - S4] = __float2half(dino[i - S1 - S2 - S3 - S4]);
    }
}

// ---------------- host orchestration ----------------
static void gemm(const __half* A, const __half* B, void* C, int M, int N, int K,
                 int ldb, int ldc, int flags)
{
    int ctas128 = (N / 128) * (M / 128);
    if (ctas128 < 256) {
        dim3 g(N / 128, M / 64);
        size_t sm = 4 * (64 * GA_STRIDE + 32 * GB_STRIDE);
        gemm_h<64><<<g, 256, sm>>>(A, B, C, M, N, K, ldb, ldc, flags);
    } else {
        dim3 g(N / 128, M / 128);
        size_t sm = 4 * (128 * GA_STRIDE + 32 * GB_STRIDE);
        gemm_h<128><<<g, 256, sm>>>(A, B, C, M, N, K, ldb, ldc, flags);
    }
}

struct Scr { __half *qkv, *oh, *hh, *t1h, *wpackh, *mWh, *w1h, *w2h; };

static void layer_tail(const float* x, float* outp, __half* outh, int M, int li,
                       const Scr& S)
{
    const __half* mW = S.mWh + (size_t)li * 256 * 256;
    const __half* w1 = S.w1h + (size_t)li * 512 * 512;
    const __half* w2 = S.w2h + (size_t)li * 512 * 256;
    gemm_ln<0><<<M / 32, 256, GLN_SMEM>>>(S.oh, mW, x, nullptr, S.hh, M, 256, 256);
    gemm(S.hh,  w1, S.t1h, M, 512, 512, 512, 512, 3);
    gemm_ln<1><<<M / 32, 256, GLN_SMEM>>>(S.t1h, w2, x, outp, outh, M, 512, 256);
}

extern "C" void kernel_launch(void* const* d_in, const int* in_sizes, int n_in,
                              void* d_out, int out_size)
{
    (void)in_sizes; (void)out_size;
    const float* in_srcF = (const float*)d_in[0];
    const float* in_tgtF = (const float*)d_in[1];
    const int*   si      = (const int*)  d_in[6];
    const int*   ti      = (const int*)  d_in[7];
    const float* src2d   = (const float*)d_in[11];
    const float* tgt2d   = (const float*)d_in[12];
    const float* w2A   = (const float*)d_in[n_in - 1];
    const float* w1A   = (const float*)d_in[n_in - 2];
    const float* mWA   = (const float*)d_in[n_in - 3];
    const float* vWA   = (const float*)d_in[n_in - 4];
    const float* kWA   = (const float*)d_in[n_in - 5];
    const float* qWA   = (const float*)d_in[n_in - 6];
    const float* dinoW = (const float*)d_in[n_in - 7];
    float* out = (float*)d_out;

    float *feat, *proj, *sub;
    __half *feath, *subh, *oh, *hh, *t1h, *qkv, *semh, *d2h;
    __half *wpackh, *mWh, *w1h, *w2h, *dinoh;
    cudaGetSymbolAddress((void**)&feat, g_feat);
    cudaGetSymbolAddress((void**)&proj, g_proj);
    cudaGetSymbolAddress((void**)&sub, g_sub);
    cudaGetSymbolAddress((void**)&feath, g_feath);
    cudaGetSymbolAddress((void**)&subh, g_subh);
    cudaGetSymbolAddress((void**)&oh, g_oh);
    cudaGetSymbolAddress((void**)&hh, g_hh);
    cudaGetSymbolAddress((void**)&t1h, g_t1h);
    cudaGetSymbolAddress((void**)&qkv, g_qkv);
    cudaGetSymbolAddress((void**)&semh, g_semh);
    cudaGetSymbolAddress((void**)&d2h, g_2dh);
    cudaGetSymbolAddress((void**)&wpackh, g_wpackh);
    cudaGetSymbolAddress((void**)&mWh, g_mWh);
    cudaGetSymbolAddress((void**)&w1h, g_w1h);
    cudaGetSymbolAddress((void**)&w2h, g_w2h);
    cudaGetSymbolAddress((void**)&dinoh, g_dinoh);

    cudaFuncSetAttribute(attn_kernel<8>, cudaFuncAttributeMaxDynamicSharedMemorySize,
                         ATTN_SMEM8);
    cudaFuncSetAttribute(attn_kernel<4>, cudaFuncAttributeMaxDynamicSharedMemorySize,
                         ATTN_SMEM4);
    cudaFuncSetAttribute(gemm_h<64>, cudaFuncAttributeMaxDynamicSharedMemorySize,
                         4 * (64 * GA_STRIDE + 32 * GB_STRIDE));
    cudaFuncSetAttribute(gemm_h<128>, cudaFuncAttributeMaxDynamicSharedMemorySize,
                         4 * (128 * GA_STRIDE + 32 * GB_STRIDE));
    cudaFuncSetAttribute(gemm_ln<0>, cudaFuncAttributeMaxDynamicSharedMemorySize,
                         GLN_SMEM);
    cudaFuncSetAttribute(gemm_ln<1>, cudaFuncAttributeMaxDynamicSharedMemorySize,
                         GLN_SMEM);

    float* featS = feat;
    float* featT = feat + (size_t)4096 * 256;
    __half* featSh = feath;
    __half* featTh = feath + (size_t)4096 * 256;
    __half* src2h = d2h;

    {
        const int TOT = 5*256*768 + 5*256*256 + 5*512*512 + 5*512*256 + 384*256;
        cvt_weights<<<(TOT + 255) / 256, 256>>>(qWA, kWA, vWA, mWA, w1A, w2A, dinoW,
                                                wpackh, mWh, w1h, w2h, dinoh);
    }
    cvt_h_kernel<<<(4096 * 384 + 255) / 256, 256>>>(src2d, src2h, 4096 * 384);
    cvt_h_kernel<<<(4096 * 384 + 255) / 256, 256>>>(tgt2d, src2h + (size_t)4096 * 384,
                                                    4096 * 384);

    Scr S{qkv, oh, hh, t1h, wpackh, mWh, w1h, w2h};
    const size_t sideBytes = (size_t)4096 * 256 * sizeof(float);

    cudaMemcpyAsync(featS, in_srcF, sideBytes, cudaMemcpyDeviceToDevice, 0);
    cudaMemcpyAsync(featT, in_tgtF, sideBytes, cudaMemcpyDeviceToDevice, 0);

    // fused projection: both sides in one M=8192 GEMM (contiguous buffers)
    gemm(src2h, dinoh, proj, 8192, 256, 384, 256, 256, 0);

    for (int li = 0; li < 4; li++) {
        const __half* packL = wpackh + (size_t)li * 256 * 768;
        if ((li & 1) == 0) {
            add_kernel<<<8192 * 256 / 256, 256>>>(feat, feath, proj, 8192 * 256);
            gemm(feath, packL, qkv, 8192, 768, 256, 768, 768, 6);
            attn_kernel<8><<<dim3(16, NHEAD, 4), 256, ATTN_SMEM8>>>(
                qkv, qkv, oh, 2048, 2048, 0);
            layer_tail(feat, feat, feath, 8192, li, S);
        } else {
            gemm(feath, packL, qkv, 8192, 768, 256, 768, 768, 6);
            attn_kernel<4><<<dim3(32, NHEAD, 2), 128, ATTN_SMEM4>>>(
                qkv, qkv, oh, 2048, 2048, 2);
            layer_tail(featS, featS, featSh, 4096, li, S);
            gemm(featSh, packL + 256, qkv + 256, 4096, 512, 256, 768, 768, 2);
            attn_kernel<4><<<dim3(32, NHEAD, 2), 128, ATTN_SMEM4>>>(
                qkv + (size_t)2 * 2048 * 768, qkv, oh, 2048, 2048, 0);
            layer_tail(featT, featT, featTh, 4096, li, S);
        }
    }

    float* ssub = sub;
    float* tsub = sub + (size_t)8192 * 256;
    __half* ssubh = subh;
    __half* tsubh = subh + (size_t)8192 * 256;
    gather_kernel<<<16 * 512, 256>>>(featS, si, ssub, ssubh, 2048, 512, 8);
    gather_kernel<<<16 * 512, 256>>>(featT, ti, tsub, tsubh, 2048, 512, 8);
    {
        const __half* packL = wpackh + (size_t)4 * 256 * 768;
        gemm(subh, packL, qkv, 16384, 768, 256, 768, 768, 6);
        attn_kernel<8><<<dim3(4, NHEAD, 32), 256, ATTN_SMEM8>>>(
            qkv, qkv, oh, 512, 512, 16);
        layer_tail(sub, out + (size_t)2 * 1048576, semh, 16384, 4, S);
    }

    cudaMemcpyAsync(out,           featS, sideBytes, cudaMemcpyDeviceToDevice, 0);
    cudaMemcpyAsync(out + 1048576, featT, sideBytes, cudaMemcpyDeviceToDevice, 0);
}